// round 3
// baseline (speedup 1.0000x reference)
#include <cuda_runtime.h>
#include <cstddef>

#define TT 4096
#define KK 16
#define BB 32
#define RHO_C 0.001f
#define NEG_INF_C (-1000000.0f)

// ---------------------------------------------------------------------------
// Kernel 1: build + write the normalized transition tensor A (B,T,K,K).
// Pure HBM-bound: 128 MB of writes. One block per (b,t), 256 threads, each
// thread writes exactly one element (coalesced 1 KB per block).
// ---------------------------------------------------------------------------
__global__ void __launch_bounds__(256) build_A_kernel(const float* __restrict__ bp,
                                                      float* __restrict__ A) {
    int bt = blockIdx.x;
    float p = bp[bt];
    float eta = fminf(fmaxf(0.02f + 0.33f * p, 0.001f), 0.95f);
    float stay = fmaxf((1.0f - eta) - RHO_C, 0.01f);
    float r0 = (1.0f - eta) + eta;            // row 0 sum
    float rm = (RHO_C + stay) + eta;          // middle row sum
    float rl = RHO_C + (1.0f - RHO_C);        // last row sum

    int i = threadIdx.x >> 4;                 // row
    int j = threadIdx.x & 15;                 // col
    float ri = (i == 0) ? r0 : ((i == 15) ? rl : rm);
    float dg = (i == 0) ? (1.0f - eta) : ((i == 15) ? (1.0f - RHO_C) : stay);

    float v = 0.0f;
    if (j == i)          v = dg / ri;
    else if (j == i + 1) v = eta / ri;
    else if (j == i - 1) v = RHO_C / ri;

    A[(size_t)bt * 256 + threadIdx.x] = v;
}

// ---------------------------------------------------------------------------
// Kernel 2: sequential forward scan, one warp per batch, 16 lanes = 16 states.
// Probability-domain recurrence with one-step-deferred normalization:
//   w_t[j] = ( e*u[j-1] + d*u[j] + r*u[j+1] + 1e-10*(c - s3) ) * E_t[j] / c
// where u = w_{t-1}, c = sum(u). The 1e-10 floor reproduces
// log(clip(A,1e-10)) exactly; wrap trick handles rows 0/15 edges.
// Outputs for step t-1 are emitted inside iteration t (c = exp(lZ_{t-1})).
// ---------------------------------------------------------------------------
__global__ void __launch_bounds__(32) scan_kernel(
    const float* __restrict__ em, const float* __restrict__ bp,
    const float* __restrict__ msk,
    float* __restrict__ bel, float* __restrict__ lbel, float* __restrict__ lnr)
{
    const int b = blockIdx.x;
    const int lane = threadIdx.x & 31;
    const int j = lane & 15;
    const unsigned FULL = 0xffffffffu;

    const float* emb = em + (size_t)b * TT * KK;
    const float* bpb = bp + (size_t)b * TT;
    const float* mkb = msk + (size_t)b * TT;
    float* belb = bel + (size_t)b * TT * KK;
    float* lbelb = lbel + (size_t)b * TT * KK;
    float* lnrb = lnr + (size_t)b * TT;

    // 8-deep register prefetch ring (hides DRAM latency)
    float em_r[8], bp_r[8], mk_r[8];
#pragma unroll
    for (int i = 0; i < 8; i++) {
        em_r[i] = emb[i * KK + j];
        bp_r[i] = bpb[i];
        mk_r[i] = mkb[i];
    }

    // ---- t = 0: exact log-domain closed form ----
    float lj0 = ((j == 0) ? 0.0f : NEG_INF_C) + em_r[0];
    float mx = lj0;
#pragma unroll
    for (int s = 8; s >= 1; s >>= 1)
        mx = fmaxf(mx, __shfl_xor_sync(FULL, mx, s, 16));
    float sm = expf(lj0 - mx);
#pragma unroll
    for (int s = 8; s >= 1; s >>= 1)
        sm += __shfl_xor_sync(FULL, sm, s, 16);
    float lZ0 = mx + logf(sm);
    float la0n = lj0 - lZ0;
    float m0 = mk_r[0];
    float la0 = m0 * la0n + (1.0f - m0) * ((j == 0) ? 0.0f : NEG_INF_C);
    float u = expf(la0);   // p0 (normalized)
    if (lane < 16) {
        belb[j] = u;
        lbelb[j] = la0;
        if (j == 0) lnrb[0] = m0 * lZ0;
    }
    float m_prev = m0;

    // R2 FIX: refill slot 0 (consumed by the t=0 prologue) with t=8's data.
    // Without this, iteration t=8 re-consumed t=0's emission/bp/mask.
    em_r[0] = emb[8 * KK + j];
    bp_r[0] = bpb[8];
    mk_r[0] = mkb[8];

    // ---- main scan: t = 1 .. T-1 ----
    for (int t = 1; t < TT; ++t) {
        int sl = t & 7;
        float emt = em_r[sl];
        float bpt = bp_r[sl];
        float mt  = mk_r[sl];
        if (t + 8 < TT) {                       // prefetch 8 steps ahead
            em_r[sl] = emb[(t + 8) * KK + j];
            bp_r[sl] = bpb[t + 8];
            mk_r[sl] = mkb[t + 8];
        }

        // per-step transition coefficients (off critical path)
        float eta = fminf(fmaxf(0.02f + 0.33f * bpt, 0.001f), 0.95f);
        float stay = fmaxf((1.0f - eta) - RHO_C, 0.01f);
        float r0 = (1.0f - eta) + eta;
        float rm = (RHO_C + stay) + eta;
        float rl = RHO_C + (1.0f - RHO_C);
        float dcoef = (j == 0)  ? __fdividef(1.0f - eta, r0)
                    : (j == 15) ? __fdividef(1.0f - RHO_C, rl)
                                : __fdividef(stay, rm);
        float ecoef = (j == 0)  ? 1e-10f : __fdividef(eta, (j == 1) ? r0 : rm);
        float rcoef = (j == 15) ? 1e-10f : __fdividef(RHO_C, (j == 14) ? rl : rm);
        float E = __expf(emt);

        // ---- critical chain ----
        float c = u;
#pragma unroll
        for (int s = 8; s >= 1; s >>= 1)
            c += __shfl_xor_sync(FULL, c, s, 16);

        float um1 = __shfl_sync(FULL, u, (j + 15) & 15, 16);
        float up1 = __shfl_sync(FULL, u, (j + 1) & 15, 16);
        float tri = ecoef * um1 + dcoef * u + rcoef * up1;
        float s3 = (um1 + u) + up1;
        float P = fmaf(1e-10f, c - s3, tri);    // dense floor term
        float ic = __fdividef(1.0f, c);
        float w = (P * E) * ic;

        // ---- outputs for step t-1 (off critical path): c = exp(lZ_{t-1}) ----
        if (t >= 2 && lane < 16) {
            float lZ = logf(c);
            belb[(t - 1) * KK + j]  = u * ic;
            lbelb[(t - 1) * KK + j] = logf(u) - lZ;
            if (j == 0) lnrb[t - 1] = m_prev * lZ;
        }
        m_prev = mt;
        u = w;
    }

    // ---- epilogue: outputs for t = T-1 ----
    float c = u;
#pragma unroll
    for (int s = 8; s >= 1; s >>= 1)
        c += __shfl_xor_sync(FULL, c, s, 16);
    float ic = __fdividef(1.0f, c);
    float lZ = logf(c);
    if (lane < 16) {
        belb[(TT - 1) * KK + j]  = u * ic;
        lbelb[(TT - 1) * KK + j] = logf(u) - lZ;
        if (j == 0) lnrb[TT - 1] = m_prev * lZ;
    }
}

// ---------------------------------------------------------------------------
// kernel_launch: outputs concatenated as (beliefs, log_beliefs,
// log_normalizers, A), all float32.
// ---------------------------------------------------------------------------
extern "C" void kernel_launch(void* const* d_in, const int* in_sizes, int n_in,
                              void* d_out, int out_size) {
    const float* em = (const float*)d_in[0];   // (B,T,K)
    const float* bp = (const float*)d_in[1];   // (B,T)
    const float* mk = (const float*)d_in[2];   // (B,T)
    float* out = (float*)d_out;

    const size_t BTK = (size_t)BB * TT * KK;
    const size_t BT  = (size_t)BB * TT;
    float* bel  = out;
    float* lbel = out + BTK;
    float* lnr  = out + 2 * BTK;
    float* A    = out + 2 * BTK + BT;

    build_A_kernel<<<BB * TT, 256>>>(bp, A);
    scan_kernel<<<BB, 32>>>(em, bp, mk, bel, lbel, lnr);
}

// round 4
// speedup vs baseline: 9.4337x; 9.4337x over previous
#include <cuda_runtime.h>
#include <cstddef>

#define TT 4096
#define KK 16
#define BB 32
#define LCH 128
#define NCH (TT / LCH)          // 32 chunks per batch
#define NCHUNK (BB * NCH)       // 1024 chunks total
#define RHO_C 0.001f
#define NEG_INF_C (-1000000.0f)
#define FLOORP 1e-10f

// Scratch (static device allocations are allowed)
__device__ float g_S[NCHUNK * 256];   // per-chunk 16x16 transfer matrix, [chunk][col][row]
__device__ float g_v0[NCHUNK * 16];   // normalized alpha entering each chunk

// ---------------------------------------------------------------------------
// Kernel: build + write the normalized transition tensor A (B,T,K,K).
// Pure HBM-bound: 128 MB of writes.
// ---------------------------------------------------------------------------
__global__ void __launch_bounds__(256) build_A_kernel(const float* __restrict__ bp,
                                                      float* __restrict__ A) {
    int bt = blockIdx.x;
    float p = bp[bt];
    float eta = fminf(fmaxf(0.02f + 0.33f * p, 0.001f), 0.95f);
    float stay = fmaxf((1.0f - eta) - RHO_C, 0.01f);
    float r0 = (1.0f - eta) + eta;
    float rm = (RHO_C + stay) + eta;
    float rl = RHO_C + (1.0f - RHO_C);

    int i = threadIdx.x >> 4;
    int j = threadIdx.x & 15;
    float ri = (i == 0) ? r0 : ((i == 15) ? rl : rm);
    float dg = (i == 0) ? (1.0f - eta) : ((i == 15) ? (1.0f - RHO_C) : stay);

    float v = 0.0f;
    if (j == i)          v = dg / ri;
    else if (j == i + 1) v = eta / ri;
    else if (j == i - 1) v = RHO_C / ri;

    A[(size_t)bt * 256 + threadIdx.x] = v;
}

// ---------------------------------------------------------------------------
// Shared staging helper logic (inlined in both phase1 and phase3):
//   s_E  : exp(emissions) for the chunk          (LCH*16 floats)
//   s_cf : per-step folded coefficients (8/step) (LCH*8 floats)
// Folded coefs have the 1e-10 floor subtracted so the step becomes
//   q = ec*u[j-1] + dc*u[j] + rc*u[j+1];  P = q + 1e-10*sum(u)
// ---------------------------------------------------------------------------

// Phase 1: per-chunk transfer matrix. One warp = 2 chunks (half-warp each);
// each lane owns one matrix column (16 rows in registers) -> no cross-lane
// work except a broadcast for the per-step rescale.
__global__ void __launch_bounds__(32) phase1_kernel(const float* __restrict__ em,
                                                    const float* __restrict__ bp) {
    __shared__ float s_E[2][LCH * KK];
    __shared__ float s_cf[2][LCH * 8];
    const unsigned FULL = 0xffffffffu;
    int lane = threadIdx.x;
    int hw = lane >> 4, c_lane = lane & 15;
    int chunk = blockIdx.x * 2 + hw;
    int b = chunk / NCH, ch = chunk % NCH;
    size_t base_t = (size_t)b * TT + (size_t)ch * LCH;

    // stage exp(emissions)
    const float4* src = (const float4*)(em + base_t * KK);
    float4* dstE = (float4*)s_E[hw];
    for (int i = c_lane; i < LCH * KK / 4; i += 16) {
        float4 v = src[i];
        dstE[i] = make_float4(__expf(v.x), __expf(v.y), __expf(v.z), __expf(v.w));
    }
    // stage folded coefficients
    for (int i = c_lane; i < LCH; i += 16) {
        float bpt = bp[base_t + i];
        float eta = fminf(fmaxf(0.02f + 0.33f * bpt, 0.001f), 0.95f);
        float stay = fmaxf((1.0f - eta) - RHO_C, 0.01f);
        float r0 = (1.0f - eta) + eta;
        float rm = (RHO_C + stay) + eta;
        float rl = RHO_C + (1.0f - RHO_C);
        float ir0 = __fdividef(1.0f, r0), irm = __fdividef(1.0f, rm), irl = __fdividef(1.0f, rl);
        float4* cf = (float4*)&s_cf[hw][i * 8];
        cf[0] = make_float4(eta * ir0 - FLOORP, eta * irm - FLOORP,
                            (1.0f - eta) * ir0 - FLOORP, stay * irm - FLOORP);
        cf[1] = make_float4((1.0f - RHO_C) * irl - FLOORP, RHO_C * irm - FLOORP,
                            RHO_C * irl - FLOORP, 0.0f);
    }
    __syncwarp();

    float w[16];
#pragma unroll
    for (int r = 0; r < 16; r++) w[r] = (r == c_lane) ? 1.0f : 0.0f;
    float csum = 1.0f;   // per-column sum of w (carried)

    int t0 = (ch == 0) ? 1 : 0;     // chunk 0: steps 1..L-1 (t=0 is closed form)
    for (int tl = t0; tl < LCH; ++tl) {
        const float4* cf = (const float4*)&s_cf[hw][tl * 8];
        float4 ca = cf[0], cb = cf[1];
        const float* Et = &s_E[hw][tl * KK];
        float y[16];
#pragma unroll
        for (int r = 0; r < 16; r++) {
            float um1 = w[(r + 15) & 15];
            float up1 = w[(r + 1) & 15];
            float ec = (r == 0) ? 0.0f : (r == 1 ? ca.x : ca.y);
            float dc = (r == 0) ? ca.z : (r == 15 ? cb.x : ca.w);
            float rc = (r == 15) ? 0.0f : (r == 14 ? cb.z : cb.y);
            float q = fmaf(dc, w[r], fmaf(rc, up1, ec * um1));
            float P = fmaf(FLOORP, csum, q);
            y[r] = P * Et[r];
        }
        float a0 = (y[0] + y[4]) + (y[8] + y[12]);
        float a1 = (y[1] + y[5]) + (y[9] + y[13]);
        float a2 = (y[2] + y[6]) + (y[10] + y[14]);
        float a3 = (y[3] + y[7]) + (y[11] + y[15]);
        float cs2 = (a0 + a1) + (a2 + a3);
        // uniform rescale by column-0's sum (keeps fp32 range; scale-invariant)
        float sc = __shfl_sync(FULL, cs2, 0, 16);
        float isc = __fdividef(1.0f, sc);
#pragma unroll
        for (int r = 0; r < 16; r++) w[r] = y[r] * isc;
        csum = cs2 * isc;
    }
    float* out = g_S + (size_t)chunk * 256 + c_lane * 16;
#pragma unroll
    for (int r = 0; r < 16; r += 4)
        *(float4*)(out + r) = make_float4(w[r], w[r + 1], w[r + 2], w[r + 3]);
}

// Phase 2: serial composition per batch — 32 normalized matvecs.
__global__ void __launch_bounds__(32) phase2_kernel(const float* __restrict__ em,
                                                    const float* __restrict__ mk) {
    int b = blockIdx.x;
    int lane = threadIdx.x;
    int j = lane & 15;
    const unsigned FULL = 0xffffffffu;

    // alpha_0: lZ0 = em[0] exactly (NEG_INF entries underflow in exp)
    float em0 = __ldg(em + (size_t)b * TT * KK);
    float emj = __ldg(em + (size_t)b * TT * KK + j);
    float m0 = __ldg(mk + (size_t)b * TT);
    float la0 = (j == 0) ? 0.0f : (NEG_INF_C + emj - em0);
    la0 = m0 * la0 + (1.0f - m0) * ((j == 0) ? 0.0f : NEG_INF_C);
    float u = expf(la0);
    if (lane < 16) g_v0[(size_t)(b * NCH) * 16 + j] = u;

    for (int i = 0; i < NCH - 1; ++i) {
        const float* Sb = g_S + (size_t)(b * NCH + i) * 256;
        float s[16];
#pragma unroll
        for (int c = 0; c < 16; c++) s[c] = Sb[c * 16 + j];   // row j of S
        float y = 0.0f;
#pragma unroll
        for (int c = 0; c < 16; c++) {
            float vc = __shfl_sync(FULL, u, c, 16);
            y = fmaf(s[c], vc, y);
        }
        float cs = y;
#pragma unroll
        for (int sft = 8; sft >= 1; sft >>= 1)
            cs += __shfl_xor_sync(FULL, cs, sft, 16);
        u = y * __fdividef(1.0f, cs);
        if (lane < 16) g_v0[(size_t)(b * NCH + i + 1) * 16 + j] = u;
    }
}

// Phase 3: re-scan each chunk from its start vector, emitting all outputs.
// State = unnormalized w (w_un of previous step); since the incoming u is
// normalized, w' = fma(1/sum(w), q_w, 1e-10) * E is exact, and sum(w) is
// exp(lZ) of the previous step -> outputs are deferred one iteration.
__global__ void __launch_bounds__(32) phase3_kernel(
    const float* __restrict__ em, const float* __restrict__ bp,
    const float* __restrict__ mk,
    float* __restrict__ bel, float* __restrict__ lbel, float* __restrict__ lnr)
{
    __shared__ float s_E[2][LCH * KK];
    __shared__ float s_cf[2][LCH * 8];
    __shared__ float s_mk[2][LCH];
    const unsigned FULL = 0xffffffffu;
    int lane = threadIdx.x;
    int hw = lane >> 4, j = lane & 15;
    int chunk = blockIdx.x * 2 + hw;
    int b = chunk / NCH, ch = chunk % NCH;
    size_t base_t = (size_t)b * TT + (size_t)ch * LCH;

    // staging (same as phase 1, plus mask)
    const float4* src = (const float4*)(em + base_t * KK);
    float4* dstE = (float4*)s_E[hw];
    for (int i = j; i < LCH * KK / 4; i += 16) {
        float4 v = src[i];
        dstE[i] = make_float4(__expf(v.x), __expf(v.y), __expf(v.z), __expf(v.w));
    }
    for (int i = j; i < LCH; i += 16) {
        float bpt = bp[base_t + i];
        float eta = fminf(fmaxf(0.02f + 0.33f * bpt, 0.001f), 0.95f);
        float stay = fmaxf((1.0f - eta) - RHO_C, 0.01f);
        float r0 = (1.0f - eta) + eta;
        float rm = (RHO_C + stay) + eta;
        float rl = RHO_C + (1.0f - RHO_C);
        float ir0 = __fdividef(1.0f, r0), irm = __fdividef(1.0f, rm), irl = __fdividef(1.0f, rl);
        float4* cf = (float4*)&s_cf[hw][i * 8];
        cf[0] = make_float4(eta * ir0 - FLOORP, eta * irm - FLOORP,
                            (1.0f - eta) * ir0 - FLOORP, stay * irm - FLOORP);
        cf[1] = make_float4((1.0f - RHO_C) * irl - FLOORP, RHO_C * irm - FLOORP,
                            RHO_C * irl - FLOORP, 0.0f);
        s_mk[hw][i] = mk[base_t + i];
    }
    __syncwarp();

    float* belb  = bel  + base_t * KK;
    float* lbelb = lbel + base_t * KK;
    float* lnrb  = lnr  + base_t;

    float w;
    int t0;
    if (ch == 0) {   // ch==0 implies hw==0: no warp collectives in this branch
        float em0 = __ldg(em + (size_t)b * TT * KK);
        float emj = __ldg(em + (size_t)b * TT * KK + j);
        float m0 = s_mk[0][0];
        float la0 = (j == 0) ? 0.0f : (NEG_INF_C + emj - em0);
        la0 = m0 * la0 + (1.0f - m0) * ((j == 0) ? 0.0f : NEG_INF_C);
        w = expf(la0);
        belb[j] = w;
        lbelb[j] = la0;
        if (j == 0) lnrb[0] = m0 * em0;   // lZ0 == em[b,0,0] exactly
        t0 = 1;
    } else {
        w = g_v0[(size_t)chunk * 16 + j];  // normalized alpha entering chunk
        t0 = 0;
    }

    for (int tl = t0; tl < LCH; ++tl) {
        const float4* cf = (const float4*)&s_cf[hw][tl * 8];
        float4 ca = cf[0], cb = cf[1];
        float E = s_E[hw][tl * KK + j];

        // critical chain: butterfly + rcp (in parallel with shuffles + q)
        float c = w;
#pragma unroll
        for (int s = 8; s >= 1; s >>= 1)
            c += __shfl_xor_sync(FULL, c, s, 16);
        float ic = __fdividef(1.0f, c);

        float um1 = __shfl_sync(FULL, w, (j + 15) & 15, 16);
        float up1 = __shfl_sync(FULL, w, (j + 1) & 15, 16);
        float ec = (j == 0) ? 0.0f : (j == 1 ? ca.x : ca.y);
        float dc = (j == 0) ? ca.z : (j == 15 ? cb.x : ca.w);
        float rc = (j == 15) ? 0.0f : (j == 14 ? cb.z : cb.y);
        float q = fmaf(dc, w, fmaf(rc, up1, ec * um1));
        float wn = fmaf(ic, q, FLOORP) * E;

        // deferred outputs for time base+tl-1 (c == exp(lZ_{t-1}))
        if (tl > t0) {
            float lZ = __logf(c);
            belb[(tl - 1) * KK + j]  = w * ic;
            lbelb[(tl - 1) * KK + j] = __logf(w) - lZ;
            if (j == 0) lnrb[tl - 1] = s_mk[hw][tl - 1] * lZ;
        }
        w = wn;
    }
    // epilogue: time base + LCH - 1
    float c = w;
#pragma unroll
    for (int s = 8; s >= 1; s >>= 1)
        c += __shfl_xor_sync(FULL, c, s, 16);
    float ic = __fdividef(1.0f, c);
    float lZ = __logf(c);
    belb[(LCH - 1) * KK + j]  = w * ic;
    lbelb[(LCH - 1) * KK + j] = __logf(w) - lZ;
    if (j == 0) lnrb[LCH - 1] = s_mk[hw][LCH - 1] * lZ;
}

// ---------------------------------------------------------------------------
extern "C" void kernel_launch(void* const* d_in, const int* in_sizes, int n_in,
                              void* d_out, int out_size) {
    const float* em = (const float*)d_in[0];   // (B,T,K)
    const float* bp = (const float*)d_in[1];   // (B,T)
    const float* mk = (const float*)d_in[2];   // (B,T)
    float* out = (float*)d_out;

    const size_t BTK = (size_t)BB * TT * KK;
    const size_t BT  = (size_t)BB * TT;
    float* bel  = out;
    float* lbel = out + BTK;
    float* lnr  = out + 2 * BTK;
    float* A    = out + 2 * BTK + BT;

    build_A_kernel<<<BB * TT, 256>>>(bp, A);
    phase1_kernel<<<NCHUNK / 2, 32>>>(em, bp);
    phase2_kernel<<<BB, 32>>>(em, mk);
    phase3_kernel<<<NCHUNK / 2, 32>>>(em, bp, mk, bel, lbel, lnr);
}

// round 5
// speedup vs baseline: 25.7463x; 2.7292x over previous
#include <cuda_runtime.h>
#include <cstddef>

#define TT 4096
#define KK 16
#define BB 32
#define LCH 64
#define NCH (TT / LCH)          // 64 chunks per batch
#define NCHUNK (BB * NCH)       // 2048 chunks total
#define RHO_C 0.001f
#define NEG_INF_C (-1000000.0f)
#define FLOORP 1e-10f

__device__ float g_S[NCHUNK * 256];   // per-chunk 16x16 transfer matrix [chunk][col][row]
__device__ float g_v0[NCHUNK * 16];   // normalized alpha entering each chunk

// ---------------------------------------------------------------------------
// build_A: 128 MB of coalesced float4 writes. One float4 per thread.
// ---------------------------------------------------------------------------
__global__ void __launch_bounds__(256) build_A_kernel(const float* __restrict__ bp,
                                                      float4* __restrict__ A4) {
    unsigned g = blockIdx.x * 256 + threadIdx.x;   // float4 index
    unsigned bt = g >> 6;                           // (b,t)
    unsigned within = g & 63;
    int i = within >> 2;                            // row
    int j0 = (within & 3) * 4;                      // first col of this float4

    float p = __ldg(bp + bt);
    float eta = fminf(fmaxf(0.02f + 0.33f * p, 0.001f), 0.95f);
    float stay = fmaxf((1.0f - eta) - RHO_C, 0.01f);
    float r0 = (1.0f - eta) + eta;
    float rm = (RHO_C + stay) + eta;
    float rl = RHO_C + (1.0f - RHO_C);

    float ri = (i == 0) ? r0 : ((i == 15) ? rl : rm);
    float dg = (i == 0) ? (1.0f - eta) : ((i == 15) ? (1.0f - RHO_C) : stay);
    float iri = __fdividef(1.0f, ri);

    float v[4];
#pragma unroll
    for (int q = 0; q < 4; q++) {
        int j = j0 + q;
        float x = 0.0f;
        if (j == i)          x = dg * iri;
        else if (j == i + 1) x = eta * iri;
        else if (j == i - 1) x = RHO_C * iri;
        v[q] = x;
    }
    A4[g] = make_float4(v[0], v[1], v[2], v[3]);
}

// ---------------------------------------------------------------------------
// Coefficient folding: the 1e-10 log-clip floor is subtracted from the
// tridiagonal coefficients so a step is  q = ec*u[j-1]+dc*u[j]+rc*u[j+1];
// P = q + 1e-10*sum(u).  (wrap trick covers rows 0/15 edges)
// ---------------------------------------------------------------------------

// Phase 1: per-chunk 16x16 transfer matrix. ONE WARP PER CHUNK; lanes 0-15
// own matrix columns, lanes 16-31 mirror (keeps shuffles converged).
__global__ void __launch_bounds__(32) phase1_kernel(const float* __restrict__ em,
                                                    const float* __restrict__ bp) {
    __shared__ float s_E[LCH * KK];
    __shared__ float s_cf[LCH * 8];
    const unsigned FULL = 0xffffffffu;
    int lane = threadIdx.x;
    int c_lane = lane & 15;
    int chunk = blockIdx.x;
    int b = chunk / NCH, ch = chunk % NCH;
    size_t base_t = (size_t)b * TT + (size_t)ch * LCH;

    const float4* src = (const float4*)(em + base_t * KK);
    float4* dstE = (float4*)s_E;
    for (int i = lane; i < LCH * KK / 4; i += 32) {
        float4 v = src[i];
        dstE[i] = make_float4(__expf(v.x), __expf(v.y), __expf(v.z), __expf(v.w));
    }
    for (int i = lane; i < LCH; i += 32) {
        float bpt = bp[base_t + i];
        float eta = fminf(fmaxf(0.02f + 0.33f * bpt, 0.001f), 0.95f);
        float stay = fmaxf((1.0f - eta) - RHO_C, 0.01f);
        float r0 = (1.0f - eta) + eta;
        float rm = (RHO_C + stay) + eta;
        float rl = RHO_C + (1.0f - RHO_C);
        float ir0 = __fdividef(1.0f, r0), irm = __fdividef(1.0f, rm), irl = __fdividef(1.0f, rl);
        float4* cf = (float4*)&s_cf[i * 8];
        cf[0] = make_float4(eta * ir0 - FLOORP, eta * irm - FLOORP,
                            (1.0f - eta) * ir0 - FLOORP, stay * irm - FLOORP);
        cf[1] = make_float4((1.0f - RHO_C) * irl - FLOORP, RHO_C * irm - FLOORP,
                            RHO_C * irl - FLOORP, 0.0f);
    }
    __syncwarp();

    float w[16];
#pragma unroll
    for (int r = 0; r < 16; r++) w[r] = (r == c_lane) ? 1.0f : 0.0f;
    float csum = 1.0f;

    int t0 = (ch == 0) ? 1 : 0;     // uniform across the warp now
    for (int tl = t0; tl < LCH; ++tl) {
        const float4* cf = (const float4*)&s_cf[tl * 8];
        float4 ca = cf[0], cb = cf[1];
        const float* Et = &s_E[tl * KK];
        float y[16];
#pragma unroll
        for (int r = 0; r < 16; r++) {
            float um1 = w[(r + 15) & 15];
            float up1 = w[(r + 1) & 15];
            float ec = (r == 0) ? 0.0f : (r == 1 ? ca.x : ca.y);
            float dc = (r == 0) ? ca.z : (r == 15 ? cb.x : ca.w);
            float rc = (r == 15) ? 0.0f : (r == 14 ? cb.z : cb.y);
            float q = fmaf(dc, w[r], fmaf(rc, up1, ec * um1));
            float P = fmaf(FLOORP, csum, q);
            y[r] = P * Et[r];
        }
        float a0 = (y[0] + y[4]) + (y[8] + y[12]);
        float a1 = (y[1] + y[5]) + (y[9] + y[13]);
        float a2 = (y[2] + y[6]) + (y[10] + y[14]);
        float a3 = (y[3] + y[7]) + (y[11] + y[15]);
        float cs2 = (a0 + a1) + (a2 + a3);
        float sc = __shfl_sync(FULL, cs2, 0, 16);   // rescale by col-0's sum
        float isc = __fdividef(1.0f, sc);
#pragma unroll
        for (int r = 0; r < 16; r++) w[r] = y[r] * isc;
        csum = cs2 * isc;
    }
    if (lane < 16) {
        float* out = g_S + (size_t)chunk * 256 + c_lane * 16;
#pragma unroll
        for (int r = 0; r < 16; r += 4)
            *(float4*)(out + r) = make_float4(w[r], w[r + 1], w[r + 2], w[r + 3]);
    }
}

// Phase 2: serial composition per batch (63 normalized matvecs, prefetched).
__global__ void __launch_bounds__(32) phase2_kernel(const float* __restrict__ em,
                                                    const float* __restrict__ mk) {
    int b = blockIdx.x;
    int lane = threadIdx.x;
    int j = lane & 15;
    const unsigned FULL = 0xffffffffu;

    float em0 = __ldg(em + (size_t)b * TT * KK);
    float emj = __ldg(em + (size_t)b * TT * KK + j);
    float m0 = __ldg(mk + (size_t)b * TT);
    float la0 = (j == 0) ? 0.0f : (NEG_INF_C + emj - em0);
    la0 = m0 * la0 + (1.0f - m0) * ((j == 0) ? 0.0f : NEG_INF_C);
    float u = expf(la0);
    if (lane < 16) g_v0[(size_t)(b * NCH) * 16 + j] = u;

    const float* Sb = g_S + (size_t)(b * NCH) * 256;
    float s[16];
#pragma unroll
    for (int c = 0; c < 16; c++) s[c] = Sb[c * 16 + j];

    for (int i = 0; i < NCH - 1; ++i) {
        float sn[16];
        if (i + 1 < NCH - 1) {
            const float* Sn = Sb + (size_t)(i + 1) * 256;
#pragma unroll
            for (int c = 0; c < 16; c++) sn[c] = Sn[c * 16 + j];
        }
        float y = 0.0f;
#pragma unroll
        for (int c = 0; c < 16; c++) {
            float vc = __shfl_sync(FULL, u, c, 16);
            y = fmaf(s[c], vc, y);
        }
        float cs = y;
#pragma unroll
        for (int sft = 8; sft >= 1; sft >>= 1)
            cs += __shfl_xor_sync(FULL, cs, sft, 16);
        u = y * __fdividef(1.0f, cs);
        if (lane < 16) g_v0[(size_t)(b * NCH + i + 1) * 16 + j] = u;
#pragma unroll
        for (int c = 0; c < 16; c++) s[c] = sn[c];
    }
}

// Phase 3: re-scan each chunk emitting all outputs. ONE WARP PER CHUNK,
// lanes 0-15 own states, 16-31 mirror. Unnormalized carry with 1/sum folded
// into the step; sum(w) = exp(lZ_{t-1}) -> outputs deferred one iteration.
__global__ void __launch_bounds__(32) phase3_kernel(
    const float* __restrict__ em, const float* __restrict__ bp,
    const float* __restrict__ mk,
    float* __restrict__ bel, float* __restrict__ lbel, float* __restrict__ lnr)
{
    __shared__ float s_E[LCH * KK];
    __shared__ float s_cf[LCH * 8];
    __shared__ float s_mk[LCH];
    const unsigned FULL = 0xffffffffu;
    int lane = threadIdx.x;
    int j = lane & 15;
    int chunk = blockIdx.x;
    int b = chunk / NCH, ch = chunk % NCH;
    size_t base_t = (size_t)b * TT + (size_t)ch * LCH;

    const float4* src = (const float4*)(em + base_t * KK);
    float4* dstE = (float4*)s_E;
    for (int i = lane; i < LCH * KK / 4; i += 32) {
        float4 v = src[i];
        dstE[i] = make_float4(__expf(v.x), __expf(v.y), __expf(v.z), __expf(v.w));
    }
    for (int i = lane; i < LCH; i += 32) {
        float bpt = bp[base_t + i];
        float eta = fminf(fmaxf(0.02f + 0.33f * bpt, 0.001f), 0.95f);
        float stay = fmaxf((1.0f - eta) - RHO_C, 0.01f);
        float r0 = (1.0f - eta) + eta;
        float rm = (RHO_C + stay) + eta;
        float rl = RHO_C + (1.0f - RHO_C);
        float ir0 = __fdividef(1.0f, r0), irm = __fdividef(1.0f, rm), irl = __fdividef(1.0f, rl);
        float4* cf = (float4*)&s_cf[i * 8];
        cf[0] = make_float4(eta * ir0 - FLOORP, eta * irm - FLOORP,
                            (1.0f - eta) * ir0 - FLOORP, stay * irm - FLOORP);
        cf[1] = make_float4((1.0f - RHO_C) * irl - FLOORP, RHO_C * irm - FLOORP,
                            RHO_C * irl - FLOORP, 0.0f);
        s_mk[i] = mk[base_t + i];
    }
    __syncwarp();

    float* belb  = bel  + base_t * KK;
    float* lbelb = lbel + base_t * KK;
    float* lnrb  = lnr  + base_t;

    float w;
    int t0;
    if (ch == 0) {                       // uniform across the warp
        float em0 = __ldg(em + (size_t)b * TT * KK);
        float emj = __ldg(em + (size_t)b * TT * KK + j);
        float m0 = s_mk[0];
        float la0 = (j == 0) ? 0.0f : (NEG_INF_C + emj - em0);
        la0 = m0 * la0 + (1.0f - m0) * ((j == 0) ? 0.0f : NEG_INF_C);
        w = expf(la0);
        if (lane < 16) {
            belb[j] = w;
            lbelb[j] = la0;
            if (j == 0) lnrb[0] = m0 * em0;   // lZ0 == em[b,0,0] exactly
        }
        t0 = 1;
    } else {
        w = g_v0[(size_t)chunk * 16 + j];
        t0 = 0;
    }

    for (int tl = t0; tl < LCH; ++tl) {
        const float4* cf = (const float4*)&s_cf[tl * 8];
        float4 ca = cf[0], cb = cf[1];
        float E = s_E[tl * KK + j];

        float c = w;                       // 16-lane butterfly (critical chain)
#pragma unroll
        for (int s = 8; s >= 1; s >>= 1)
            c += __shfl_xor_sync(FULL, c, s, 16);
        float ic = __fdividef(1.0f, c);

        float um1 = __shfl_sync(FULL, w, (j + 15) & 15, 16);
        float up1 = __shfl_sync(FULL, w, (j + 1) & 15, 16);
        float ec = (j == 0) ? 0.0f : (j == 1 ? ca.x : ca.y);
        float dc = (j == 0) ? ca.z : (j == 15 ? cb.x : ca.w);
        float rc = (j == 15) ? 0.0f : (j == 14 ? cb.z : cb.y);
        float q = fmaf(dc, w, fmaf(rc, up1, ec * um1));
        float wn = fmaf(ic, q, FLOORP) * E;

        if (tl > t0 && lane < 16) {        // deferred outputs for t = base+tl-1
            float lZ = __logf(c);
            belb[(tl - 1) * KK + j]  = w * ic;
            lbelb[(tl - 1) * KK + j] = __logf(w) - lZ;
            if (j == 0) lnrb[tl - 1] = s_mk[tl - 1] * lZ;
        }
        w = wn;
    }
    float c = w;
#pragma unroll
    for (int s = 8; s >= 1; s >>= 1)
        c += __shfl_xor_sync(FULL, c, s, 16);
    float ic = __fdividef(1.0f, c);
    if (lane < 16) {
        float lZ = __logf(c);
        belb[(LCH - 1) * KK + j]  = w * ic;
        lbelb[(LCH - 1) * KK + j] = __logf(w) - lZ;
        if (j == 0) lnrb[LCH - 1] = s_mk[LCH - 1] * lZ;
    }
}

// ---------------------------------------------------------------------------
extern "C" void kernel_launch(void* const* d_in, const int* in_sizes, int n_in,
                              void* d_out, int out_size) {
    const float* em = (const float*)d_in[0];
    const float* bp = (const float*)d_in[1];
    const float* mk = (const float*)d_in[2];
    float* out = (float*)d_out;

    const size_t BTK = (size_t)BB * TT * KK;
    const size_t BT  = (size_t)BB * TT;
    float* bel  = out;
    float* lbel = out + BTK;
    float* lnr  = out + 2 * BTK;
    float* A    = out + 2 * BTK + BT;

    build_A_kernel<<<(BB * TT * 64) / 256, 256>>>(bp, (float4*)A);
    phase1_kernel<<<NCHUNK, 32>>>(em, bp);
    phase2_kernel<<<BB, 32>>>(em, mk);
    phase3_kernel<<<NCHUNK, 32>>>(em, bp, mk, bel, lbel, lnr);
}